// round 4
// baseline (speedup 1.0000x reference)
#include <cuda_runtime.h>
#include <cuda_bf16.h>
#include <math.h>
#include <stdint.h>

#define B_SZ 4096
#define T_SZ 80
#define E_SZ 100
#define U_SZ 1024
#define V_SZ 10000

// CTA tile
#define BM 128
#define BN 128
#define BK 128            // K bytes (=elements, int8) per stage
// smem stage layout: 4 planes of 128 rows x 128B, SW128 swizzled
#define A_A 0
#define A_B 16384
#define B_C 32768
#define B_D 49152
#define STAGE 65536
#define SMEM_DYN (2 * STAGE + 1024)

#define ALPHA 0.015625f    // 1/64
#define BETA  0.0078125f   // 1/128

// ---------------------------------------------------------------------------
// Scratch (__device__ globals)
// ---------------------------------------------------------------------------
__device__ __align__(16) int8_t g_wq[6][U_SZ * U_SZ];   // Wh0(c,d), Wx1(c,d), Wh1(c,d), [n][k]
__device__ __align__(16) float  g_gam[2][U_SZ];         // per-col scales: layer0, layer1(shared)
__device__ __align__(16) float  g_xw0[V_SZ * U_SZ];     // emb@Wx0 + b0
__device__ __align__(16) int8_t g_hq[8][B_SZ * U_SZ];   // h0 a/b ping, a/b pong, h1 ...

// ---------------------------------------------------------------------------
// helpers
// ---------------------------------------------------------------------------
__device__ __forceinline__ uint32_t smem_u32(const void* p) {
    uint32_t a;
    asm("{ .reg .u64 t; cvta.to.shared.u64 t, %1; cvt.u32.u64 %0, t; }"
        : "=r"(a) : "l"(p));
    return a;
}
__device__ __forceinline__ uint32_t swz128(uint32_t off) {
    return off ^ ((off >> 3) & 0x70);
}
__device__ __forceinline__ void cpa16(uint32_t dst, const void* src) {
    asm volatile("cp.async.cg.shared.global [%0], [%1], 16;" :: "r"(dst), "l"(src));
}
__device__ __forceinline__ void ldsm4(uint32_t* r, uint32_t addr) {
    asm volatile("ldmatrix.sync.aligned.m8n8.x4.shared.b16 {%0,%1,%2,%3}, [%4];"
                 : "=r"(r[0]), "=r"(r[1]), "=r"(r[2]), "=r"(r[3]) : "r"(addr));
}
__device__ __forceinline__ void mma_s8(int* c, const uint32_t* a, const uint32_t* b) {
    asm volatile(
        "mma.sync.aligned.m16n8k32.row.col.s32.s8.s8.s32 "
        "{%0,%1,%2,%3}, {%4,%5,%6,%7}, {%8,%9}, {%0,%1,%2,%3};"
        : "+r"(c[0]), "+r"(c[1]), "+r"(c[2]), "+r"(c[3])
        : "r"(a[0]), "r"(a[1]), "r"(a[2]), "r"(a[3]), "r"(b[0]), "r"(b[1]));
}
__device__ __forceinline__ float fast_tanh(float x) {
    float e = __expf(-2.0f * fabsf(x));
    float t = __fdividef(1.0f - e, 1.0f + e);
    return copysignf(t, x);
}

// ---------------------------------------------------------------------------
// Main step kernel (int8 split GEMM):
//   D = sum over nseg segments of [ ACC1 = a.c ; ACC2 = a.d + b.c ]
//   y = ALPHA*gamma[n]*(ACC1 + BETA*ACC2) + (xw0 gather | bias)
//   h = tanh(y)  -> quantize to (a,b) int8 planes
// ---------------------------------------------------------------------------
__global__ void __launch_bounds__(256, 1)
rnn_step_kernel(const int8_t* __restrict__ A0a, const int8_t* __restrict__ A0b,
                const int8_t* __restrict__ W0c, const int8_t* __restrict__ W0d,
                const int8_t* __restrict__ A1a, const int8_t* __restrict__ A1b,
                const int8_t* __restrict__ W1c, const int8_t* __restrict__ W1d,
                int nseg,
                const float* __restrict__ gamma,
                const float* __restrict__ bias,   // layer-1 only
                const float* __restrict__ xw0,    // non-null for layer 0
                const int* __restrict__ inputs, int t,
                int8_t* __restrict__ outa, int8_t* __restrict__ outb) {
    extern __shared__ char dsm[];
    const uint32_t tile = (smem_u32(dsm) + 1023u) & ~1023u;

    const int tid = threadIdx.x;
    const int wid = tid >> 5;
    const int lane = tid & 31;
    const int m0 = blockIdx.y * BM;
    const int n0 = blockIdx.x * BN;

    const int mW = (wid & 1) * 64;     // 2 warps along M
    const int nW = (wid >> 1) * 32;    // 4 warps along N

    const int8_t* __restrict__ Aa[2] = {A0a, A1a};
    const int8_t* __restrict__ Ab[2] = {A0b, A1b};
    const int8_t* __restrict__ Wc[2] = {W0c, W1c};
    const int8_t* __restrict__ Wd[2] = {W0d, W1d};

    const int NST = nseg * (U_SZ / BK);    // 8 or 16 stages

    // per-thread staging indices: 128 rows x 8 sixteen-byte chunks per plane
    int lrow[4], lcol[4];
    uint32_t ldst[4];
#pragma unroll
    for (int i = 0; i < 4; ++i) {
        int c = tid + i * 256;
        lrow[i] = c >> 3;
        lcol[i] = (c & 7) * 16;
        ldst[i] = swz128((uint32_t)(lrow[i] * 128 + lcol[i]));
    }

    auto load_stage = [&](int s, int buf) {
        const int seg = s >> 3;
        const int k0 = (s & 7) * BK;
        const uint32_t bb = tile + (uint32_t)buf * STAGE;
        const int8_t* aa = Aa[seg];
        const int8_t* ab = Ab[seg];
        const int8_t* wc = Wc[seg];
        const int8_t* wd = Wd[seg];
#pragma unroll
        for (int i = 0; i < 4; ++i) {
            size_t ga = (size_t)(m0 + lrow[i]) * U_SZ + k0 + lcol[i];
            size_t gb = (size_t)(n0 + lrow[i]) * U_SZ + k0 + lcol[i];
            cpa16(bb + A_A + ldst[i], aa + ga);
            cpa16(bb + A_B + ldst[i], ab + ga);
            cpa16(bb + B_C + ldst[i], wc + gb);
            cpa16(bb + B_D + ldst[i], wd + gb);
        }
        asm volatile("cp.async.commit_group;" ::: "memory");
    };

    int acc1[4][4][4], acc2[4][4][4];
#pragma unroll
    for (int i = 0; i < 4; ++i)
#pragma unroll
        for (int j = 0; j < 4; ++j)
#pragma unroll
            for (int q = 0; q < 4; ++q) { acc1[i][j][q] = 0; acc2[i][j][q] = 0; }

    // ldmatrix source addressing (bytes; k chunk = 32B per ks)
    const int a_row = mW + (lane & 15);
    const int a_cg  = (lane >> 4) * 16;
    const int b_q   = lane >> 3;
    const int b_row = nW + ((b_q >> 1) * 8) + (lane & 7);
    const int b_cg  = (b_q & 1) * 16;

    load_stage(0, 0);

    for (int s = 0; s < NST; ++s) {
        const int buf = s & 1;
        if (s + 1 < NST) {
            load_stage(s + 1, buf ^ 1);
            asm volatile("cp.async.wait_group 1;" ::: "memory");
        } else {
            asm volatile("cp.async.wait_group 0;" ::: "memory");
        }
        __syncthreads();

        const uint32_t bb = tile + (uint32_t)buf * STAGE;
#pragma unroll
        for (int ks = 0; ks < 4; ++ks) {
            uint32_t af[4][4], cf[4][2], df[4][2];
#pragma unroll
            for (int j2 = 0; j2 < 2; ++j2) {
                uint32_t off = swz128((uint32_t)((b_row + j2 * 16) * 128 + ks * 32 + b_cg));
                uint32_t r[4];
                ldsm4(r, bb + B_C + off);
                cf[j2 * 2][0] = r[0]; cf[j2 * 2][1] = r[1];
                cf[j2 * 2 + 1][0] = r[2]; cf[j2 * 2 + 1][1] = r[3];
                ldsm4(r, bb + B_D + off);
                df[j2 * 2][0] = r[0]; df[j2 * 2][1] = r[1];
                df[j2 * 2 + 1][0] = r[2]; df[j2 * 2 + 1][1] = r[3];
            }
#pragma unroll
            for (int i = 0; i < 4; ++i) {
                uint32_t off = swz128((uint32_t)((a_row + i * 16) * 128 + ks * 32 + a_cg));
                ldsm4(af[i], bb + A_A + off);
            }
#pragma unroll
            for (int i = 0; i < 4; ++i)
#pragma unroll
                for (int j = 0; j < 4; ++j)
                    mma_s8(acc1[i][j], af[i], cf[j]);
#pragma unroll
            for (int i = 0; i < 4; ++i)
#pragma unroll
                for (int j = 0; j < 4; ++j)
                    mma_s8(acc2[i][j], af[i], df[j]);
            // reuse af for the 'b' plane
#pragma unroll
            for (int i = 0; i < 4; ++i) {
                uint32_t off = swz128((uint32_t)((a_row + i * 16) * 128 + ks * 32 + a_cg));
                ldsm4(af[i], bb + A_B + off);
            }
#pragma unroll
            for (int i = 0; i < 4; ++i)
#pragma unroll
                for (int j = 0; j < 4; ++j)
                    mma_s8(acc2[i][j], af[i], cf[j]);
        }
        __syncthreads();
    }

    // ---- epilogue ----
    const int gp = lane >> 2;
    const int t4 = lane & 3;
#pragma unroll
    for (int i = 0; i < 4; ++i) {
#pragma unroll
        for (int rh = 0; rh < 2; ++rh) {
            const int m = m0 + mW + i * 16 + gp + rh * 8;
            const float* xr = nullptr;
            if (xw0) xr = xw0 + (size_t)inputs[(size_t)m * T_SZ + t] * U_SZ;
#pragma unroll
            for (int j = 0; j < 4; ++j) {
                const int col = n0 + nW + j * 8 + t4 * 2;
                float g0 = gamma[col], g1 = gamma[col + 1];
                float v0 = ((float)acc1[i][j][rh * 2 + 0] +
                            BETA * (float)acc2[i][j][rh * 2 + 0]) * (ALPHA * g0);
                float v1 = ((float)acc1[i][j][rh * 2 + 1] +
                            BETA * (float)acc2[i][j][rh * 2 + 1]) * (ALPHA * g1);
                if (xr) { v0 += xr[col]; v1 += xr[col + 1]; }
                else    { v0 += bias[col]; v1 += bias[col + 1]; }
                float h0 = fast_tanh(v0), h1 = fast_tanh(v1);
                // quantize: h = (a + b/128)/64
                float a0 = rintf(h0 * 64.0f), a1 = rintf(h1 * 64.0f);
                int qa0 = (int)a0, qa1 = (int)a1;
                int qb0 = (int)rintf((h0 - a0 * ALPHA) * 8192.0f);
                int qb1 = (int)rintf((h1 - a1 * ALPHA) * 8192.0f);
                uint16_t pa = (uint16_t)((qa0 & 0xFF) | ((qa1 & 0xFF) << 8));
                uint16_t pb = (uint16_t)((qb0 & 0xFF) | ((qb1 & 0xFF) << 8));
                *(uint16_t*)(outa + (size_t)m * U_SZ + col) = pa;
                *(uint16_t*)(outb + (size_t)m * U_SZ + col) = pb;
            }
        }
    }
}

// ---------------------------------------------------------------------------
// Prep: per-column scale + int8 hi/lo quantization, transposed to [n][k].
// blockIdx.y: 0 -> Wh0 (gamma0); 1 -> {Wx1, Wh1} shared gamma1.
// ---------------------------------------------------------------------------
__global__ void __launch_bounds__(256)
wquant_kernel(const float* __restrict__ Wh0, const float* __restrict__ Wx1,
              const float* __restrict__ Wh1) {
    __shared__ float smax[8][32];
    __shared__ float sg[32];
    __shared__ int8_t sc[32][32];
    __shared__ int8_t sd[32][32];

    const int tx = threadIdx.x & 31;
    const int ty = threadIdx.x >> 5;
    const int n = blockIdx.x * 32 + tx;
    const int set = blockIdx.y;

    float m = 1e-20f;
    if (set == 0) {
        for (int k = ty; k < U_SZ; k += 8)
            m = fmaxf(m, fabsf(Wh0[(size_t)k * U_SZ + n]));
    } else {
        for (int k = ty; k < U_SZ; k += 8) {
            m = fmaxf(m, fabsf(Wx1[(size_t)k * U_SZ + n]));
            m = fmaxf(m, fabsf(Wh1[(size_t)k * U_SZ + n]));
        }
    }
    smax[ty][tx] = m;
    __syncthreads();
    if (ty == 0) {
        float mm = smax[0][tx];
#pragma unroll
        for (int r = 1; r < 8; ++r) mm = fmaxf(mm, smax[r][tx]);
        float g = mm * (1.0f / 127.0f);
        sg[tx] = g;
        g_gam[set][n] = g;
    }
    __syncthreads();
    const float g = sg[tx];
    const float invg = 1.0f / g;

    const int nmats = (set == 0) ? 1 : 2;
    for (int mi = 0; mi < nmats; ++mi) {
        const float* W = (set == 0) ? Wh0 : (mi == 0 ? Wx1 : Wh1);
        int8_t* Pc = g_wq[set == 0 ? 0 : (mi == 0 ? 2 : 4)];
        int8_t* Pd = g_wq[set == 0 ? 1 : (mi == 0 ? 3 : 5)];
        for (int kc = 0; kc < U_SZ / 32; ++kc) {
#pragma unroll
            for (int q = 0; q < 4; ++q) {
                int k = kc * 32 + ty * 4 + q;
                float w = W[(size_t)k * U_SZ + n];
                float cf = rintf(w * invg);
                float r = w - cf * g;
                float dfv = rintf(r * invg * 128.0f);
                sc[ty * 4 + q][tx] = (int8_t)(int)cf;
                sd[ty * 4 + q][tx] = (int8_t)(int)dfv;
            }
            __syncthreads();
            // write 32 rows x 32 k-bytes, coalesced-ish as u32
            {
                int nl = threadIdx.x >> 3;
                int wrd = threadIdx.x & 7;
                uint32_t vc = (uint8_t)sc[wrd * 4 + 0][nl] |
                              ((uint8_t)sc[wrd * 4 + 1][nl] << 8) |
                              ((uint8_t)sc[wrd * 4 + 2][nl] << 16) |
                              ((uint8_t)sc[wrd * 4 + 3][nl] << 24);
                uint32_t vd = (uint8_t)sd[wrd * 4 + 0][nl] |
                              ((uint8_t)sd[wrd * 4 + 1][nl] << 8) |
                              ((uint8_t)sd[wrd * 4 + 2][nl] << 16) |
                              ((uint8_t)sd[wrd * 4 + 3][nl] << 24);
                size_t off = (size_t)(blockIdx.x * 32 + nl) * U_SZ + kc * 32 + wrd * 4;
                *(uint32_t*)(Pc + off) = vc;
                *(uint32_t*)(Pd + off) = vd;
            }
            __syncthreads();
        }
    }
}

// ---------------------------------------------------------------------------
// Prep: xw0[v][n] = b0[n] + sum_k emb[v,k] * Wx0[k,n]
// ---------------------------------------------------------------------------
__global__ void __launch_bounds__(256)
xw0_kernel(const float* __restrict__ emb, const float* __restrict__ Wx0,
           const float* __restrict__ b0, float* __restrict__ xw0) {
    __shared__ float es[16][104];
    const int v0 = blockIdx.y * 16;
    const int n = blockIdx.x * 256 + threadIdx.x;
    for (int i = threadIdx.x; i < 16 * E_SZ; i += 256) {
        int r = i / E_SZ, c = i % E_SZ;
        es[r][c] = emb[(size_t)(v0 + r) * E_SZ + c];
    }
    __syncthreads();
    float acc[16];
    float bv = b0[n];
#pragma unroll
    for (int i = 0; i < 16; ++i) acc[i] = bv;
    for (int k = 0; k < E_SZ; ++k) {
        float w = Wx0[(size_t)k * U_SZ + n];
#pragma unroll
        for (int i = 0; i < 16; ++i) acc[i] = fmaf(es[i][k], w, acc[i]);
    }
#pragma unroll
    for (int i = 0; i < 16; ++i)
        xw0[(size_t)(v0 + i) * U_SZ + n] = acc[i];
}

// ---------------------------------------------------------------------------
__global__ void zero4_kernel(int8_t* a, int8_t* b, int8_t* c, int8_t* d) {
    size_t i = (size_t)blockIdx.x * blockDim.x + threadIdx.x;  // uint4 index
    uint4 z = make_uint4(0, 0, 0, 0);
    ((uint4*)a)[i] = z; ((uint4*)b)[i] = z;
    ((uint4*)c)[i] = z; ((uint4*)d)[i] = z;
}

// ---------------------------------------------------------------------------
__global__ void __launch_bounds__(256)
final_kernel(const int8_t* __restrict__ h1a, const int8_t* __restrict__ h1b,
             const float* __restrict__ Wfc, const float* __restrict__ bfc,
             float* __restrict__ out) {
    int warp = (blockIdx.x * blockDim.x + threadIdx.x) >> 5;
    int lane = threadIdx.x & 31;
    if (warp >= B_SZ) return;
    float s = 0.0f;
#pragma unroll
    for (int u = lane; u < U_SZ; u += 32) {
        float h = ((float)h1a[(size_t)warp * U_SZ + u] +
                   (float)h1b[(size_t)warp * U_SZ + u] * BETA) * ALPHA;
        s = fmaf(h, Wfc[u], s);
    }
#pragma unroll
    for (int o = 16; o > 0; o >>= 1) s += __shfl_xor_sync(0xffffffffu, s, o);
    if (lane == 0) {
        float z = s + bfc[0];
        out[warp] = 1.0f / (1.0f + expf(-z));
    }
}

// ---------------------------------------------------------------------------
extern "C" void kernel_launch(void* const* d_in, const int* in_sizes, int n_in,
                              void* d_out, int out_size) {
    const int*   inputs = (const int*)  d_in[0];
    const float* emb    = (const float*)d_in[1];
    const float* Wx0    = (const float*)d_in[2];
    const float* Wh0    = (const float*)d_in[3];
    const float* b0     = (const float*)d_in[4];
    const float* Wx1    = (const float*)d_in[5];
    const float* Wh1    = (const float*)d_in[6];
    const float* b1     = (const float*)d_in[7];
    const float* Wfc    = (const float*)d_in[8];
    const float* bfc    = (const float*)d_in[9];
    float* out = (float*)d_out;

    cudaFuncSetAttribute(rnn_step_kernel,
                         cudaFuncAttributeMaxDynamicSharedMemorySize, SMEM_DYN);

    int8_t *wq, *hq;
    float *xw0, *gam;
    cudaGetSymbolAddress((void**)&wq, g_wq);
    cudaGetSymbolAddress((void**)&hq, g_hq);
    cudaGetSymbolAddress((void**)&xw0, g_xw0);
    cudaGetSymbolAddress((void**)&gam, g_gam);

    const size_t WS = (size_t)U_SZ * U_SZ;
    int8_t* Wh0c = wq + 0 * WS; int8_t* Wh0d = wq + 1 * WS;
    int8_t* Wx1c = wq + 2 * WS; int8_t* Wx1d = wq + 3 * WS;
    int8_t* Wh1c = wq + 4 * WS; int8_t* Wh1d = wq + 5 * WS;
    float* gam0 = gam;
    float* gam1 = gam + U_SZ;

    const size_t HS = (size_t)B_SZ * U_SZ;
    int8_t* h0[2][2] = {{hq + 0 * HS, hq + 1 * HS}, {hq + 2 * HS, hq + 3 * HS}};
    int8_t* h1[2][2] = {{hq + 4 * HS, hq + 5 * HS}, {hq + 6 * HS, hq + 7 * HS}};

    wquant_kernel<<<dim3(U_SZ / 32, 2), 256>>>(Wh0, Wx1, Wh1);
    xw0_kernel<<<dim3(4, V_SZ / 16), 256>>>(emb, Wx0, b0, xw0);
    zero4_kernel<<<(unsigned)(HS / 16 / 256), 256>>>(h0[0][0], h0[0][1], h1[0][0], h1[0][1]);

    dim3 grid(U_SZ / BN, B_SZ / BM);   // (8, 32) = 256 CTAs

    int p0 = 0, p1 = 0;
    for (int t = 0; t < T_SZ; ++t) {
        rnn_step_kernel<<<grid, 256, SMEM_DYN>>>(
            h0[p0][0], h0[p0][1], Wh0c, Wh0d,
            nullptr, nullptr, nullptr, nullptr, 1,
            gam0, nullptr, xw0, inputs, t,
            h0[p0 ^ 1][0], h0[p0 ^ 1][1]);
        p0 ^= 1;
        rnn_step_kernel<<<grid, 256, SMEM_DYN>>>(
            h0[p0][0], h0[p0][1], Wx1c, Wx1d,
            h1[p1][0], h1[p1][1], Wh1c, Wh1d, 2,
            gam1, b1, nullptr, nullptr, 0,
            h1[p1 ^ 1][0], h1[p1 ^ 1][1]);
        p1 ^= 1;
    }

    final_kernel<<<B_SZ / 8, 256>>>(h1[p1][0], h1[p1][1], Wfc, bfc, out);
}

// round 5
// speedup vs baseline: 4.0700x; 4.0700x over previous
#include <cuda_runtime.h>
#include <cuda_fp16.h>
#include <math.h>
#include <stdint.h>

#define B_SZ 4096
#define T_SZ 80
#define E_SZ 100
#define U_SZ 1024
#define V_SZ 10000

// CTA tile
#define BM 128
#define BN 128
#define BK 64
// smem stage layout (each plane: 128 rows x 128B, SW128 swizzled)
#define A_PL 0
#define B_HI 16384
#define B_LO 32768
#define STAGE 49152
#define SMEM_DYN (2 * STAGE + 1024)

// ---------------------------------------------------------------------------
// Scratch (__device__ globals)
// ---------------------------------------------------------------------------
__device__ __align__(16) __half g_wt[6][U_SZ * U_SZ];  // Wh0,Wx1,Wh1 (hi,lo), [n][k]
__device__ __align__(16) float  g_xw0[V_SZ * U_SZ];    // emb@Wx0 + b0
__device__ __align__(16) __half g_h[4][B_SZ * U_SZ];   // h0 ping/pong, h1 ping/pong

// ---------------------------------------------------------------------------
// helpers
// ---------------------------------------------------------------------------
__device__ __forceinline__ uint32_t smem_u32(const void* p) {
    uint32_t a;
    asm("{ .reg .u64 t; cvta.to.shared.u64 t, %1; cvt.u32.u64 %0, t; }"
        : "=r"(a) : "l"(p));
    return a;
}
__device__ __forceinline__ uint32_t swz128(uint32_t off) {
    return off ^ ((off >> 3) & 0x70);
}
__device__ __forceinline__ void cpa16(uint32_t dst, const void* src) {
    asm volatile("cp.async.cg.shared.global [%0], [%1], 16;" :: "r"(dst), "l"(src));
}
__device__ __forceinline__ void ldsm4(uint32_t* r, uint32_t addr) {
    asm volatile("ldmatrix.sync.aligned.m8n8.x4.shared.b16 {%0,%1,%2,%3}, [%4];"
                 : "=r"(r[0]), "=r"(r[1]), "=r"(r[2]), "=r"(r[3]) : "r"(addr));
}
__device__ __forceinline__ void mma16816(float* c, const uint32_t* a, const uint32_t* b) {
    asm volatile(
        "mma.sync.aligned.m16n8k16.row.col.f32.f16.f16.f32 "
        "{%0,%1,%2,%3}, {%4,%5,%6,%7}, {%8,%9}, {%0,%1,%2,%3};"
        : "+f"(c[0]), "+f"(c[1]), "+f"(c[2]), "+f"(c[3])
        : "r"(a[0]), "r"(a[1]), "r"(a[2]), "r"(a[3]), "r"(b[0]), "r"(b[1]));
}

// ---------------------------------------------------------------------------
// Main step kernel: D[128x128] = sum over nseg segments of A(fp16) x
// (Whi + Wlo) [n][k]; epilogue tanh(D + xw0_gather|bias) -> fp16 state.
// ---------------------------------------------------------------------------
__global__ void __launch_bounds__(256, 1)
rnn_step_kernel(const __half* __restrict__ A0, const __half* __restrict__ W0hi,
                const __half* __restrict__ W0lo,
                const __half* __restrict__ A1, const __half* __restrict__ W1hi,
                const __half* __restrict__ W1lo,
                int nseg,
                const float* __restrict__ bias,   // layer-1 only
                const float* __restrict__ xw0,    // non-null for layer 0
                const int* __restrict__ inputs, int t,
                __half* __restrict__ outp) {
    extern __shared__ char dsm[];
    const uint32_t tile = (smem_u32(dsm) + 1023u) & ~1023u;

    const int tid = threadIdx.x;
    const int wid = tid >> 5;
    const int lane = tid & 31;
    const int m0 = blockIdx.y * BM;
    const int n0 = blockIdx.x * BN;

    const int mW = (wid & 1) * 64;     // 2 warps along M
    const int nW = (wid >> 1) * 32;    // 4 warps along N

    const __half* __restrict__ Ap[2] = {A0, A1};
    const __half* __restrict__ Wh[2] = {W0hi, W1hi};
    const __half* __restrict__ Wl[2] = {W0lo, W1lo};

    const int NST = nseg * (U_SZ / BK);    // 16 or 32 stages

    // per-thread staging indices: 128 rows x 8 sixteen-byte chunks per plane
    int lrow[4], lcol[4];
    uint32_t ldst[4];
#pragma unroll
    for (int i = 0; i < 4; ++i) {
        int c = tid + i * 256;
        lrow[i] = c >> 3;
        lcol[i] = c & 7;
        ldst[i] = swz128((uint32_t)(lrow[i] * 128 + lcol[i] * 16));
    }

    auto load_stage = [&](int s, int buf) {
        const int seg = s >> 4;
        const int k0 = (s & 15) * BK;
        const uint32_t bb = tile + (uint32_t)buf * STAGE;
        const __half* ap = Ap[seg];
        const __half* wh = Wh[seg];
        const __half* wl = Wl[seg];
#pragma unroll
        for (int i = 0; i < 4; ++i) {
            size_t ga = (size_t)(m0 + lrow[i]) * U_SZ + k0 + lcol[i] * 8;
            size_t gb = (size_t)(n0 + lrow[i]) * U_SZ + k0 + lcol[i] * 8;
            cpa16(bb + A_PL + ldst[i], ap + ga);
            cpa16(bb + B_HI + ldst[i], wh + gb);
            cpa16(bb + B_LO + ldst[i], wl + gb);
        }
        asm volatile("cp.async.commit_group;" ::: "memory");
    };

    float acc[4][4][4];
#pragma unroll
    for (int i = 0; i < 4; ++i)
#pragma unroll
        for (int j = 0; j < 4; ++j)
#pragma unroll
            for (int q = 0; q < 4; ++q) acc[i][j][q] = 0.0f;

    // per-warp ldmatrix source offsets
    const int a_row = mW + (lane & 15);
    const int a_cg  = (lane >> 4) * 16;
    const int b_q   = lane >> 3;
    const int b_row = nW + ((b_q >> 1) * 8) + (lane & 7);
    const int b_cg  = (b_q & 1) * 16;

    load_stage(0, 0);

    for (int s = 0; s < NST; ++s) {
        const int buf = s & 1;
        if (s + 1 < NST) {
            load_stage(s + 1, buf ^ 1);
            asm volatile("cp.async.wait_group 1;" ::: "memory");
        } else {
            asm volatile("cp.async.wait_group 0;" ::: "memory");
        }
        __syncthreads();

        const uint32_t bb = tile + (uint32_t)buf * STAGE;
#pragma unroll
        for (int ks = 0; ks < 4; ++ks) {
            uint32_t af[4][4], bh4[4][2], bl4[4][2];
#pragma unroll
            for (int i = 0; i < 4; ++i) {
                uint32_t off = swz128((uint32_t)((a_row + i * 16) * 128 + ks * 32 + a_cg));
                ldsm4(af[i], bb + A_PL + off);
            }
#pragma unroll
            for (int j2 = 0; j2 < 2; ++j2) {
                uint32_t off = swz128((uint32_t)((b_row + j2 * 16) * 128 + ks * 32 + b_cg));
                uint32_t r[4];
                ldsm4(r, bb + B_HI + off);
                bh4[j2 * 2][0] = r[0]; bh4[j2 * 2][1] = r[1];
                bh4[j2 * 2 + 1][0] = r[2]; bh4[j2 * 2 + 1][1] = r[3];
                ldsm4(r, bb + B_LO + off);
                bl4[j2 * 2][0] = r[0]; bl4[j2 * 2][1] = r[1];
                bl4[j2 * 2 + 1][0] = r[2]; bl4[j2 * 2 + 1][1] = r[3];
            }
#pragma unroll
            for (int i = 0; i < 4; ++i)
#pragma unroll
                for (int j = 0; j < 4; ++j)
                    mma16816(acc[i][j], af[i], bh4[j]);
#pragma unroll
            for (int i = 0; i < 4; ++i)
#pragma unroll
                for (int j = 0; j < 4; ++j)
                    mma16816(acc[i][j], af[i], bl4[j]);
        }
        __syncthreads();
    }

    // ---- epilogue ----
    const int gp = lane >> 2;
    const int t4 = lane & 3;
#pragma unroll
    for (int i = 0; i < 4; ++i) {
#pragma unroll
        for (int rh = 0; rh < 2; ++rh) {
            const int m = m0 + mW + i * 16 + gp + rh * 8;
            const float* xr = nullptr;
            if (xw0) xr = xw0 + (size_t)inputs[(size_t)m * T_SZ + t] * U_SZ;
#pragma unroll
            for (int j = 0; j < 4; ++j) {
                const int col = n0 + nW + j * 8 + t4 * 2;
                float v0 = acc[i][j][rh * 2 + 0];
                float v1 = acc[i][j][rh * 2 + 1];
                if (xr) { v0 += xr[col]; v1 += xr[col + 1]; }
                else    { v0 += bias[col]; v1 += bias[col + 1]; }
                __half h0 = __float2half_rn(tanhf(v0));
                __half h1 = __float2half_rn(tanhf(v1));
                uint32_t p = (uint32_t)__half_as_ushort(h0) |
                             ((uint32_t)__half_as_ushort(h1) << 16);
                *(uint32_t*)(outp + (size_t)m * U_SZ + col) = p;
            }
        }
    }
}

// ---------------------------------------------------------------------------
// Prep: transpose + fp16-split the three recurrent weight matrices
// ---------------------------------------------------------------------------
__global__ void __launch_bounds__(256)
transpose_split_kernel(const float* __restrict__ W0, const float* __restrict__ W1,
                       const float* __restrict__ W2) {
    __shared__ float tilebuf[32][33];
    const int z = blockIdx.z;
    const float* W = (z == 0) ? W0 : ((z == 1) ? W1 : W2);
    __half* Th = g_wt[2 * z];
    __half* Tl = g_wt[2 * z + 1];
    const int tx = threadIdx.x & 31, ty = threadIdx.x >> 5;
    const int x = blockIdx.x * 32 + tx;
    const int y0 = blockIdx.y * 32;
#pragma unroll
    for (int j = 0; j < 32; j += 8)
        tilebuf[ty + j][tx] = W[(size_t)(y0 + ty + j) * U_SZ + x];
    __syncthreads();
    const int x2 = blockIdx.y * 32 + tx;
#pragma unroll
    for (int j = 0; j < 32; j += 8) {
        int n = blockIdx.x * 32 + ty + j;
        float v = tilebuf[tx][ty + j];
        __half h = __float2half_rn(v);
        Th[(size_t)n * U_SZ + x2] = h;
        Tl[(size_t)n * U_SZ + x2] = __float2half_rn(v - __half2float(h));
    }
}

// ---------------------------------------------------------------------------
// Prep: xw0[v][n] = b0[n] + sum_k emb[v,k] * Wx0[k,n]
// ---------------------------------------------------------------------------
__global__ void __launch_bounds__(256)
xw0_kernel(const float* __restrict__ emb, const float* __restrict__ Wx0,
           const float* __restrict__ b0, float* __restrict__ xw0) {
    __shared__ float es[16][104];
    const int v0 = blockIdx.y * 16;
    const int n = blockIdx.x * 256 + threadIdx.x;
    for (int i = threadIdx.x; i < 16 * E_SZ; i += 256) {
        int r = i / E_SZ, c = i % E_SZ;
        es[r][c] = emb[(size_t)(v0 + r) * E_SZ + c];
    }
    __syncthreads();
    float acc[16];
    float bv = b0[n];
#pragma unroll
    for (int i = 0; i < 16; ++i) acc[i] = bv;
    for (int k = 0; k < E_SZ; ++k) {
        float w = Wx0[(size_t)k * U_SZ + n];
#pragma unroll
        for (int i = 0; i < 16; ++i) acc[i] = fmaf(es[i][k], w, acc[i]);
    }
#pragma unroll
    for (int i = 0; i < 16; ++i)
        xw0[(size_t)(v0 + i) * U_SZ + n] = acc[i];
}

// ---------------------------------------------------------------------------
__global__ void zero2_kernel(__half* a, __half* b) {
    size_t i = (size_t)blockIdx.x * blockDim.x + threadIdx.x;
    uint4 z = make_uint4(0, 0, 0, 0);
    ((uint4*)a)[i] = z; ((uint4*)b)[i] = z;
}

// ---------------------------------------------------------------------------
__global__ void __launch_bounds__(256)
final_kernel(const __half* __restrict__ h1, const float* __restrict__ Wfc,
             const float* __restrict__ bfc, float* __restrict__ out) {
    int warp = (blockIdx.x * blockDim.x + threadIdx.x) >> 5;
    int lane = threadIdx.x & 31;
    if (warp >= B_SZ) return;
    float s = 0.0f;
#pragma unroll
    for (int u = lane; u < U_SZ; u += 32)
        s = fmaf(__half2float(h1[(size_t)warp * U_SZ + u]), Wfc[u], s);
#pragma unroll
    for (int o = 16; o > 0; o >>= 1) s += __shfl_xor_sync(0xffffffffu, s, o);
    if (lane == 0) {
        float z = s + bfc[0];
        out[warp] = 1.0f / (1.0f + expf(-z));
    }
}

// ---------------------------------------------------------------------------
extern "C" void kernel_launch(void* const* d_in, const int* in_sizes, int n_in,
                              void* d_out, int out_size) {
    const int*   inputs = (const int*)  d_in[0];
    const float* emb    = (const float*)d_in[1];
    const float* Wx0    = (const float*)d_in[2];
    const float* Wh0    = (const float*)d_in[3];
    const float* b0     = (const float*)d_in[4];
    const float* Wx1    = (const float*)d_in[5];
    const float* Wh1    = (const float*)d_in[6];
    const float* b1     = (const float*)d_in[7];
    const float* Wfc    = (const float*)d_in[8];
    const float* bfc    = (const float*)d_in[9];
    float* out = (float*)d_out;

    cudaFuncSetAttribute(rnn_step_kernel,
                         cudaFuncAttributeMaxDynamicSharedMemorySize, SMEM_DYN);

    __half *wt, *h;
    float* xw0;
    cudaGetSymbolAddress((void**)&wt, g_wt);
    cudaGetSymbolAddress((void**)&xw0, g_xw0);
    cudaGetSymbolAddress((void**)&h, g_h);

    const size_t WS = (size_t)U_SZ * U_SZ;
    __half* Wh0h = wt + 0 * WS; __half* Wh0l = wt + 1 * WS;
    __half* Wx1h = wt + 2 * WS; __half* Wx1l = wt + 3 * WS;
    __half* Wh1h = wt + 4 * WS; __half* Wh1l = wt + 5 * WS;

    const size_t HS = (size_t)B_SZ * U_SZ;
    __half* h0[2] = {h + 0 * HS, h + 1 * HS};
    __half* h1[2] = {h + 2 * HS, h + 3 * HS};

    transpose_split_kernel<<<dim3(32, 32, 3), 256>>>(Wh0, Wx1, Wh1);
    xw0_kernel<<<dim3(4, V_SZ / 16), 256>>>(emb, Wx0, b0, xw0);
    zero2_kernel<<<(unsigned)(HS / 8 / 256), 256>>>(h0[0], h1[0]);

    dim3 grid(U_SZ / BN, B_SZ / BM);   // (8, 32) = 256 CTAs

    int p0 = 0, p1 = 0;
    for (int t = 0; t < T_SZ; ++t) {
        rnn_step_kernel<<<grid, 256, SMEM_DYN>>>(
            h0[p0], Wh0h, Wh0l,
            nullptr, nullptr, nullptr, 1,
            nullptr, xw0, inputs, t,
            h0[p0 ^ 1]);
        p0 ^= 1;
        rnn_step_kernel<<<grid, 256, SMEM_DYN>>>(
            h0[p0], Wx1h, Wx1l,
            h1[p1], Wh1h, Wh1l, 2,
            b1, nullptr, nullptr, 0,
            h1[p1 ^ 1]);
        p1 ^= 1;
    }

    final_kernel<<<B_SZ / 8, 256>>>(h1[p1], Wfc, bfc, out);
}

// round 6
// speedup vs baseline: 4.5840x; 1.1263x over previous
#include <cuda_runtime.h>
#include <cuda_fp16.h>
#include <math.h>
#include <stdint.h>

#define B_SZ 4096
#define T_SZ 80
#define E_SZ 100
#define U_SZ 1024
#define V_SZ 10000

// CTA tile 128x128, BK=64, 128 threads (4 warps, each 64x64)
#define BM 128
#define BN 128
#define BK 64
#define A_PL 0
#define B_HI 16384
#define B_LO 32768
#define STAGE 49152
#define SMEM_DYN (2 * STAGE + 1024)

// ---------------------------------------------------------------------------
// Scratch (__device__ globals)
// ---------------------------------------------------------------------------
__device__ __align__(16) __half g_wt[6][U_SZ * U_SZ];  // Wh0,Wx1,Wh1 (hi,lo), [n][k]
__device__ __align__(16) float  g_xw0[V_SZ * U_SZ];    // emb@Wx0 + b0
__device__ __align__(16) __half g_h[4][B_SZ * U_SZ];   // h0 ping/pong, h1 ping/pong

// ---------------------------------------------------------------------------
// helpers
// ---------------------------------------------------------------------------
__device__ __forceinline__ uint32_t smem_u32(const void* p) {
    uint32_t a;
    asm("{ .reg .u64 t; cvta.to.shared.u64 t, %1; cvt.u32.u64 %0, t; }"
        : "=r"(a) : "l"(p));
    return a;
}
__device__ __forceinline__ uint32_t swz128(uint32_t off) {
    return off ^ ((off >> 3) & 0x70);
}
__device__ __forceinline__ void cpa16(uint32_t dst, const void* src) {
    asm volatile("cp.async.cg.shared.global [%0], [%1], 16;" :: "r"(dst), "l"(src));
}
__device__ __forceinline__ void ldsm4(uint32_t* r, uint32_t addr) {
    asm volatile("ldmatrix.sync.aligned.m8n8.x4.shared.b16 {%0,%1,%2,%3}, [%4];"
                 : "=r"(r[0]), "=r"(r[1]), "=r"(r[2]), "=r"(r[3]) : "r"(addr));
}
__device__ __forceinline__ void mma16816(float* c, const uint32_t* a, const uint32_t* b) {
    asm volatile(
        "mma.sync.aligned.m16n8k16.row.col.f32.f16.f16.f32 "
        "{%0,%1,%2,%3}, {%4,%5,%6,%7}, {%8,%9}, {%0,%1,%2,%3};"
        : "+f"(c[0]), "+f"(c[1]), "+f"(c[2]), "+f"(c[3])
        : "r"(a[0]), "r"(a[1]), "r"(a[2]), "r"(a[3]), "r"(b[0]), "r"(b[1]));
}

// ---------------------------------------------------------------------------
// Step kernel: D[128x128] = sum over nseg segments of A(fp16) @ (Whi + Wlo)
// epilogue: tanh(D + xw0_gather|bias) -> fp16 state.
// ---------------------------------------------------------------------------
__global__ void __launch_bounds__(128)
rnn_step_kernel(const __half* __restrict__ A0, const __half* __restrict__ W0hi,
                const __half* __restrict__ W0lo,
                const __half* __restrict__ A1, const __half* __restrict__ W1hi,
                const __half* __restrict__ W1lo,
                int nseg,
                const float* __restrict__ bias,   // layer-1 only
                const float* __restrict__ xw0,    // non-null for layer 0
                const int* __restrict__ inputs, int t,
                __half* __restrict__ outp) {
    extern __shared__ char dsm[];
    const uint32_t tile = (smem_u32(dsm) + 1023u) & ~1023u;

    const int tid = threadIdx.x;
    const int wid = tid >> 5;
    const int lane = tid & 31;
    const int m0 = blockIdx.y * BM;
    const int n0 = blockIdx.x * BN;

    const int mW = (wid & 1) * 64;     // 2 warps along M
    const int nW = (wid >> 1) * 64;    // 2 warps along N

    const __half* __restrict__ Ap[2] = {A0, A1};
    const __half* __restrict__ Wh[2] = {W0hi, W1hi};
    const __half* __restrict__ Wl[2] = {W0lo, W1lo};

    const int NST = nseg * (U_SZ / BK);    // 16 or 32 stages

    // staging indices: each plane 128 rows x 8 chunks of 16B; 8 chunks/thread/plane
    int lrow[8], lcol[8];
    uint32_t ldst[8];
#pragma unroll
    for (int i = 0; i < 8; ++i) {
        int c = tid + i * 128;
        lrow[i] = c >> 3;
        lcol[i] = c & 7;
        ldst[i] = swz128((uint32_t)(lrow[i] * 128 + lcol[i] * 16));
    }

    auto load_stage = [&](int s, int buf) {
        const int seg = s >> 4;
        const int k0 = (s & 15) * BK;
        const uint32_t bb = tile + (uint32_t)buf * STAGE;
        const __half* ap = Ap[seg];
        const __half* wh = Wh[seg];
        const __half* wl = Wl[seg];
#pragma unroll
        for (int i = 0; i < 8; ++i) {
            size_t ga = (size_t)(m0 + lrow[i]) * U_SZ + k0 + lcol[i] * 8;
            size_t gb = (size_t)(n0 + lrow[i]) * U_SZ + k0 + lcol[i] * 8;
            cpa16(bb + A_PL + ldst[i], ap + ga);
            cpa16(bb + B_HI + ldst[i], wh + gb);
            cpa16(bb + B_LO + ldst[i], wl + gb);
        }
        asm volatile("cp.async.commit_group;" ::: "memory");
    };

    float acc[4][8][4];
#pragma unroll
    for (int i = 0; i < 4; ++i)
#pragma unroll
        for (int j = 0; j < 8; ++j)
#pragma unroll
            for (int q = 0; q < 4; ++q) acc[i][j][q] = 0.0f;

    // per-warp ldmatrix source offsets
    const int a_row = mW + (lane & 15);
    const int a_cg  = (lane >> 4) * 16;
    const int b_q   = lane >> 3;
    const int b_row = nW + ((b_q >> 1) * 8) + (lane & 7);
    const int b_cg  = (b_q & 1) * 16;

    load_stage(0, 0);

    for (int s = 0; s < NST; ++s) {
        const int buf = s & 1;
        if (s + 1 < NST) {
            load_stage(s + 1, buf ^ 1);
            asm volatile("cp.async.wait_group 1;" ::: "memory");
        } else {
            asm volatile("cp.async.wait_group 0;" ::: "memory");
        }
        __syncthreads();

        const uint32_t bb = tile + (uint32_t)buf * STAGE;
#pragma unroll
        for (int ks = 0; ks < 4; ++ks) {
            uint32_t af[4][4], bh4[8][2], bl4[8][2];
#pragma unroll
            for (int i = 0; i < 4; ++i) {
                uint32_t off = swz128((uint32_t)((a_row + i * 16) * 128 + ks * 32 + a_cg));
                ldsm4(af[i], bb + A_PL + off);
            }
#pragma unroll
            for (int j2 = 0; j2 < 4; ++j2) {
                uint32_t off = swz128((uint32_t)((b_row + j2 * 16) * 128 + ks * 32 + b_cg));
                uint32_t r[4];
                ldsm4(r, bb + B_HI + off);
                bh4[j2 * 2][0] = r[0]; bh4[j2 * 2][1] = r[1];
                bh4[j2 * 2 + 1][0] = r[2]; bh4[j2 * 2 + 1][1] = r[3];
                ldsm4(r, bb + B_LO + off);
                bl4[j2 * 2][0] = r[0]; bl4[j2 * 2][1] = r[1];
                bl4[j2 * 2 + 1][0] = r[2]; bl4[j2 * 2 + 1][1] = r[3];
            }
#pragma unroll
            for (int i = 0; i < 4; ++i)
#pragma unroll
                for (int j = 0; j < 8; ++j)
                    mma16816(acc[i][j], af[i], bh4[j]);
#pragma unroll
            for (int i = 0; i < 4; ++i)
#pragma unroll
                for (int j = 0; j < 8; ++j)
                    mma16816(acc[i][j], af[i], bl4[j]);
        }
        __syncthreads();
    }

    // ---- epilogue ----
    const int gp = lane >> 2;
    const int t4 = lane & 3;
#pragma unroll
    for (int i = 0; i < 4; ++i) {
#pragma unroll
        for (int rh = 0; rh < 2; ++rh) {
            const int m = m0 + mW + i * 16 + gp + rh * 8;
            const float* xr = nullptr;
            if (xw0) xr = xw0 + (size_t)inputs[(size_t)m * T_SZ + t] * U_SZ;
#pragma unroll
            for (int j = 0; j < 8; ++j) {
                const int col = n0 + nW + j * 8 + t4 * 2;
                float v0 = acc[i][j][rh * 2 + 0];
                float v1 = acc[i][j][rh * 2 + 1];
                if (xr) { v0 += xr[col]; v1 += xr[col + 1]; }
                else    { v0 += bias[col]; v1 += bias[col + 1]; }
                __half h0 = __float2half_rn(tanhf(v0));
                __half h1 = __float2half_rn(tanhf(v1));
                uint32_t p = (uint32_t)__half_as_ushort(h0) |
                             ((uint32_t)__half_as_ushort(h1) << 16);
                *(uint32_t*)(outp + (size_t)m * U_SZ + col) = p;
            }
        }
    }
}

// ---------------------------------------------------------------------------
// Prep: transpose + fp16-split the three recurrent weight matrices
// ---------------------------------------------------------------------------
__global__ void __launch_bounds__(256)
transpose_split_kernel(const float* __restrict__ W0, const float* __restrict__ W1,
                       const float* __restrict__ W2) {
    __shared__ float tilebuf[32][33];
    const int z = blockIdx.z;
    const float* W = (z == 0) ? W0 : ((z == 1) ? W1 : W2);
    __half* Th = g_wt[2 * z];
    __half* Tl = g_wt[2 * z + 1];
    const int tx = threadIdx.x & 31, ty = threadIdx.x >> 5;
    const int x = blockIdx.x * 32 + tx;
    const int y0 = blockIdx.y * 32;
#pragma unroll
    for (int j = 0; j < 32; j += 8)
        tilebuf[ty + j][tx] = W[(size_t)(y0 + ty + j) * U_SZ + x];
    __syncthreads();
    const int x2 = blockIdx.y * 32 + tx;
#pragma unroll
    for (int j = 0; j < 32; j += 8) {
        int n = blockIdx.x * 32 + ty + j;
        float v = tilebuf[tx][ty + j];
        __half h = __float2half_rn(v);
        Th[(size_t)n * U_SZ + x2] = h;
        Tl[(size_t)n * U_SZ + x2] = __float2half_rn(v - __half2float(h));
    }
}

// ---------------------------------------------------------------------------
// Prep: xw0[v][n] = b0[n] + sum_k emb[v,k] * Wx0[k,n]
// ---------------------------------------------------------------------------
__global__ void __launch_bounds__(256)
xw0_kernel(const float* __restrict__ emb, const float* __restrict__ Wx0,
           const float* __restrict__ b0, float* __restrict__ xw0) {
    __shared__ float es[16][104];
    const int v0 = blockIdx.y * 16;
    const int n = blockIdx.x * 256 + threadIdx.x;
    for (int i = threadIdx.x; i < 16 * E_SZ; i += 256) {
        int r = i / E_SZ, c = i % E_SZ;
        es[r][c] = emb[(size_t)(v0 + r) * E_SZ + c];
    }
    __syncthreads();
    float acc[16];
    float bv = b0[n];
#pragma unroll
    for (int i = 0; i < 16; ++i) acc[i] = bv;
    for (int k = 0; k < E_SZ; ++k) {
        float w = Wx0[(size_t)k * U_SZ + n];
#pragma unroll
        for (int i = 0; i < 16; ++i) acc[i] = fmaf(es[i][k], w, acc[i]);
    }
#pragma unroll
    for (int i = 0; i < 16; ++i)
        xw0[(size_t)(v0 + i) * U_SZ + n] = acc[i];
}

// ---------------------------------------------------------------------------
__global__ void zero2_kernel(__half* a, __half* b) {
    size_t i = (size_t)blockIdx.x * blockDim.x + threadIdx.x;
    uint4 z = make_uint4(0, 0, 0, 0);
    ((uint4*)a)[i] = z; ((uint4*)b)[i] = z;
}

// ---------------------------------------------------------------------------
__global__ void __launch_bounds__(256)
final_kernel(const __half* __restrict__ h1, const float* __restrict__ Wfc,
             const float* __restrict__ bfc, float* __restrict__ out) {
    int warp = (blockIdx.x * blockDim.x + threadIdx.x) >> 5;
    int lane = threadIdx.x & 31;
    if (warp >= B_SZ) return;
    float s = 0.0f;
#pragma unroll
    for (int u = lane; u < U_SZ; u += 32)
        s = fmaf(__half2float(h1[(size_t)warp * U_SZ + u]), Wfc[u], s);
#pragma unroll
    for (int o = 16; o > 0; o >>= 1) s += __shfl_xor_sync(0xffffffffu, s, o);
    if (lane == 0) {
        float z = s + bfc[0];
        out[warp] = 1.0f / (1.0f + expf(-z));
    }
}

// ---------------------------------------------------------------------------
extern "C" void kernel_launch(void* const* d_in, const int* in_sizes, int n_in,
                              void* d_out, int out_size) {
    const int*   inputs = (const int*)  d_in[0];
    const float* emb    = (const float*)d_in[1];
    const float* Wx0    = (const float*)d_in[2];
    const float* Wh0    = (const float*)d_in[3];
    const float* b0     = (const float*)d_in[4];
    const float* Wx1    = (const float*)d_in[5];
    const float* Wh1    = (const float*)d_in[6];
    const float* b1     = (const float*)d_in[7];
    const float* Wfc    = (const float*)d_in[8];
    const float* bfc    = (const float*)d_in[9];
    float* out = (float*)d_out;

    cudaFuncSetAttribute(rnn_step_kernel,
                         cudaFuncAttributeMaxDynamicSharedMemorySize, SMEM_DYN);

    __half *wt, *h;
    float* xw0;
    cudaGetSymbolAddress((void**)&wt, g_wt);
    cudaGetSymbolAddress((void**)&xw0, g_xw0);
    cudaGetSymbolAddress((void**)&h, g_h);

    const size_t WS = (size_t)U_SZ * U_SZ;
    __half* Wh0h = wt + 0 * WS; __half* Wh0l = wt + 1 * WS;
    __half* Wx1h = wt + 2 * WS; __half* Wx1l = wt + 3 * WS;
    __half* Wh1h = wt + 4 * WS; __half* Wh1l = wt + 5 * WS;

    const size_t HS = (size_t)B_SZ * U_SZ;
    __half* h0[2] = {h + 0 * HS, h + 1 * HS};
    __half* h1[2] = {h + 2 * HS, h + 3 * HS};

    transpose_split_kernel<<<dim3(32, 32, 3), 256>>>(Wh0, Wx1, Wh1);
    xw0_kernel<<<dim3(4, V_SZ / 16), 256>>>(emb, Wx0, b0, xw0);
    zero2_kernel<<<(unsigned)(HS / 8 / 256), 256>>>(h0[0], h1[0]);

    dim3 grid(U_SZ / BN, B_SZ / BM);   // (8, 32) = 256 CTAs = one wave at 2 CTA/SM

    int p0 = 0, p1 = 0;
    for (int t = 0; t < T_SZ; ++t) {
        rnn_step_kernel<<<grid, 128, SMEM_DYN>>>(
            h0[p0], Wh0h, Wh0l,
            nullptr, nullptr, nullptr, 1,
            nullptr, xw0, inputs, t,
            h0[p0 ^ 1]);
        p0 ^= 1;
        rnn_step_kernel<<<grid, 128, SMEM_DYN>>>(
            h0[p0], Wx1h, Wx1l,
            h1[p1], Wh1h, Wh1l, 2,
            b1, nullptr, nullptr, 0,
            h1[p1 ^ 1]);
        p1 ^= 1;
    }

    final_kernel<<<B_SZ / 8, 256>>>(h1[p1], Wfc, bfc, out);
}

// round 7
// speedup vs baseline: 7.2452x; 1.5805x over previous
#include <cuda_runtime.h>
#include <cuda_fp16.h>
#include <math.h>
#include <stdint.h>

#define B_SZ 4096
#define T_SZ 80
#define E_SZ 100
#define U_SZ 1024
#define V_SZ 10000

// CTA tile 128x128, BK=64, 128 threads (4 warps, each 64x64), 3-stage ring
#define BM 128
#define BN 128
#define BK 64
#define A_PL 0
#define B_PL 16384
#define STAGE 32768
#define NBUF 3
#define SMEM_DYN (NBUF * STAGE + 1024)

// ---------------------------------------------------------------------------
// Scratch (__device__ globals)
// ---------------------------------------------------------------------------
__device__ __align__(16) __half g_wt[3][U_SZ * U_SZ];  // Wh0, Wx1, Wh1 fp16 [n][k]
__device__ __align__(16) float  g_xw0[V_SZ * U_SZ];    // emb@Wx0 + b0
__device__ __align__(16) __half g_h[4][B_SZ * U_SZ];   // h0 ping/pong, h1 ping/pong

// ---------------------------------------------------------------------------
// helpers
// ---------------------------------------------------------------------------
__device__ __forceinline__ uint32_t smem_u32(const void* p) {
    uint32_t a;
    asm("{ .reg .u64 t; cvta.to.shared.u64 t, %1; cvt.u32.u64 %0, t; }"
        : "=r"(a) : "l"(p));
    return a;
}
__device__ __forceinline__ uint32_t swz128(uint32_t off) {
    return off ^ ((off >> 3) & 0x70);
}
__device__ __forceinline__ void cpa16(uint32_t dst, const void* src) {
    asm volatile("cp.async.cg.shared.global [%0], [%1], 16;" :: "r"(dst), "l"(src));
}
__device__ __forceinline__ void ldsm4(uint32_t* r, uint32_t addr) {
    asm volatile("ldmatrix.sync.aligned.m8n8.x4.shared.b16 {%0,%1,%2,%3}, [%4];"
                 : "=r"(r[0]), "=r"(r[1]), "=r"(r[2]), "=r"(r[3]) : "r"(addr));
}
__device__ __forceinline__ void mma16816(float* c, const uint32_t* a, const uint32_t* b) {
    asm volatile(
        "mma.sync.aligned.m16n8k16.row.col.f32.f16.f16.f32 "
        "{%0,%1,%2,%3}, {%4,%5,%6,%7}, {%8,%9}, {%0,%1,%2,%3};"
        : "+f"(c[0]), "+f"(c[1]), "+f"(c[2]), "+f"(c[3])
        : "r"(a[0]), "r"(a[1]), "r"(a[2]), "r"(a[3]), "r"(b[0]), "r"(b[1]));
}

// ---------------------------------------------------------------------------
// Step kernel: D[128x128] = sum over nseg segments of A(fp16) @ W(fp16) [n][k]
// epilogue: tanh(D + xw0_gather|bias) -> fp16 state.
// ---------------------------------------------------------------------------
__global__ void __launch_bounds__(128, 2)
rnn_step_kernel(const __half* __restrict__ A0, const __half* __restrict__ W0,
                const __half* __restrict__ A1, const __half* __restrict__ W1,
                int nseg,
                const float* __restrict__ bias,   // layer-1 only
                const float* __restrict__ xw0,    // non-null for layer 0
                const int* __restrict__ inputs, int t,
                __half* __restrict__ outp) {
    extern __shared__ char dsm[];
    const uint32_t tile = (smem_u32(dsm) + 1023u) & ~1023u;

    const int tid = threadIdx.x;
    const int wid = tid >> 5;
    const int lane = tid & 31;
    const int m0 = blockIdx.y * BM;
    const int n0 = blockIdx.x * BN;

    const int mW = (wid & 1) * 64;     // 2 warps along M
    const int nW = (wid >> 1) * 64;    // 2 warps along N

    const __half* __restrict__ Ap[2] = {A0, A1};
    const __half* __restrict__ Wp[2] = {W0, W1};

    const int NST = nseg * (U_SZ / BK);    // 16 or 32 stages

    // staging: each plane 128 rows x 8 chunks of 16B = 1024 chunks; 8/thread
    int lrow[8], lcol[8];
    uint32_t ldst[8];
#pragma unroll
    for (int i = 0; i < 8; ++i) {
        int c = tid + i * 128;
        lrow[i] = c >> 3;
        lcol[i] = c & 7;
        ldst[i] = swz128((uint32_t)(lrow[i] * 128 + lcol[i] * 16));
    }

    auto load_stage = [&](int s) {
        const int seg = s >> 4;
        const int k0 = (s & 15) * BK;
        const uint32_t bb = tile + (uint32_t)(s % NBUF) * STAGE;
        const __half* ap = Ap[seg];
        const __half* wp = Wp[seg];
#pragma unroll
        for (int i = 0; i < 8; ++i) {
            size_t ga = (size_t)(m0 + lrow[i]) * U_SZ + k0 + lcol[i] * 8;
            size_t gb = (size_t)(n0 + lrow[i]) * U_SZ + k0 + lcol[i] * 8;
            cpa16(bb + A_PL + ldst[i], ap + ga);
            cpa16(bb + B_PL + ldst[i], wp + gb);
        }
        asm volatile("cp.async.commit_group;" ::: "memory");
    };

    float acc[4][8][4];
#pragma unroll
    for (int i = 0; i < 4; ++i)
#pragma unroll
        for (int j = 0; j < 8; ++j)
#pragma unroll
            for (int q = 0; q < 4; ++q) acc[i][j][q] = 0.0f;

    // per-warp ldmatrix source offsets
    const int a_row = mW + (lane & 15);
    const int a_cg  = (lane >> 4) * 16;
    const int b_q   = lane >> 3;
    const int b_row = nW + ((b_q >> 1) * 8) + (lane & 7);
    const int b_cg  = (b_q & 1) * 16;

    load_stage(0);
    load_stage(1);

    for (int s = 0; s < NST; ++s) {
        if (s + 1 < NST) {
            asm volatile("cp.async.wait_group 1;" ::: "memory");
        } else {
            asm volatile("cp.async.wait_group 0;" ::: "memory");
        }
        // one barrier per stage: confirms stage-s data visible to all warps AND
        // that every warp finished computing stage s-1 (frees buffer (s+2)%3)
        __syncthreads();
        if (s + 2 < NST) load_stage(s + 2);

        const uint32_t bb = tile + (uint32_t)(s % NBUF) * STAGE;
#pragma unroll
        for (int ks = 0; ks < 4; ++ks) {
            uint32_t af[4][4], bf[8][2];
#pragma unroll
            for (int i = 0; i < 4; ++i) {
                uint32_t off = swz128((uint32_t)((a_row + i * 16) * 128 + ks * 32 + a_cg));
                ldsm4(af[i], bb + A_PL + off);
            }
#pragma unroll
            for (int j2 = 0; j2 < 4; ++j2) {
                uint32_t off = swz128((uint32_t)((b_row + j2 * 16) * 128 + ks * 32 + b_cg));
                uint32_t r[4];
                ldsm4(r, bb + B_PL + off);
                bf[j2 * 2][0] = r[0]; bf[j2 * 2][1] = r[1];
                bf[j2 * 2 + 1][0] = r[2]; bf[j2 * 2 + 1][1] = r[3];
            }
#pragma unroll
            for (int i = 0; i < 4; ++i)
#pragma unroll
                for (int j = 0; j < 8; ++j)
                    mma16816(acc[i][j], af[i], bf[j]);
        }
    }

    // ---- epilogue ----
    const int gp = lane >> 2;
    const int t4 = lane & 3;
#pragma unroll
    for (int i = 0; i < 4; ++i) {
#pragma unroll
        for (int rh = 0; rh < 2; ++rh) {
            const int m = m0 + mW + i * 16 + gp + rh * 8;
            const float* xr = nullptr;
            if (xw0) xr = xw0 + (size_t)inputs[(size_t)m * T_SZ + t] * U_SZ;
#pragma unroll
            for (int j = 0; j < 8; ++j) {
                const int col = n0 + nW + j * 8 + t4 * 2;
                float v0 = acc[i][j][rh * 2 + 0];
                float v1 = acc[i][j][rh * 2 + 1];
                if (xr) { v0 += xr[col]; v1 += xr[col + 1]; }
                else    { v0 += bias[col]; v1 += bias[col + 1]; }
                __half h0 = __float2half_rn(tanhf(v0));
                __half h1 = __float2half_rn(tanhf(v1));
                uint32_t p = (uint32_t)__half_as_ushort(h0) |
                             ((uint32_t)__half_as_ushort(h1) << 16);
                *(uint32_t*)(outp + (size_t)m * U_SZ + col) = p;
            }
        }
    }
}

// ---------------------------------------------------------------------------
// Prep: transpose the three recurrent weight matrices to fp16 [n][k]
// ---------------------------------------------------------------------------
__global__ void __launch_bounds__(256)
transpose_split_kernel(const float* __restrict__ W0, const float* __restrict__ W1,
                       const float* __restrict__ W2) {
    __shared__ float tilebuf[32][33];
    const int z = blockIdx.z;
    const float* W = (z == 0) ? W0 : ((z == 1) ? W1 : W2);
    __half* Th = g_wt[z];
    const int tx = threadIdx.x & 31, ty = threadIdx.x >> 5;
    const int x = blockIdx.x * 32 + tx;
    const int y0 = blockIdx.y * 32;
#pragma unroll
    for (int j = 0; j < 32; j += 8)
        tilebuf[ty + j][tx] = W[(size_t)(y0 + ty + j) * U_SZ + x];
    __syncthreads();
    const int x2 = blockIdx.y * 32 + tx;
#pragma unroll
    for (int j = 0; j < 32; j += 8) {
        int n = blockIdx.x * 32 + ty + j;
        Th[(size_t)n * U_SZ + x2] = __float2half_rn(tilebuf[tx][ty + j]);
    }
}

// ---------------------------------------------------------------------------
// Prep: xw0[v][n] = b0[n] + sum_k emb[v,k] * Wx0[k,n]
// ---------------------------------------------------------------------------
__global__ void __launch_bounds__(256)
xw0_kernel(const float* __restrict__ emb, const float* __restrict__ Wx0,
           const float* __restrict__ b0, float* __restrict__ xw0) {
    __shared__ float es[16][104];
    const int v0 = blockIdx.y * 16;
    const int n = blockIdx.x * 256 + threadIdx.x;
    for (int i = threadIdx.x; i < 16 * E_SZ; i += 256) {
        int r = i / E_SZ, c = i % E_SZ;
        es[r][c] = emb[(size_t)(v0 + r) * E_SZ + c];
    }
    __syncthreads();
    float acc[16];
    float bv = b0[n];
#pragma unroll
    for (int i = 0; i < 16; ++i) acc[i] = bv;
    for (int k = 0; k < E_SZ; ++k) {
        float w = Wx0[(size_t)k * U_SZ + n];
#pragma unroll
        for (int i = 0; i < 16; ++i) acc[i] = fmaf(es[i][k], w, acc[i]);
    }
#pragma unroll
    for (int i = 0; i < 16; ++i)
        xw0[(size_t)(v0 + i) * U_SZ + n] = acc[i];
}

// ---------------------------------------------------------------------------
__global__ void zero2_kernel(__half* a, __half* b) {
    size_t i = (size_t)blockIdx.x * blockDim.x + threadIdx.x;
    uint4 z = make_uint4(0, 0, 0, 0);
    ((uint4*)a)[i] = z; ((uint4*)b)[i] = z;
}

// ---------------------------------------------------------------------------
__global__ void __launch_bounds__(256)
final_kernel(const __half* __restrict__ h1, const float* __restrict__ Wfc,
             const float* __restrict__ bfc, float* __restrict__ out) {
    int warp = (blockIdx.x * blockDim.x + threadIdx.x) >> 5;
    int lane = threadIdx.x & 31;
    if (warp >= B_SZ) return;
    float s = 0.0f;
#pragma unroll
    for (int u = lane; u < U_SZ; u += 32)
        s = fmaf(__half2float(h1[(size_t)warp * U_SZ + u]), Wfc[u], s);
#pragma unroll
    for (int o = 16; o > 0; o >>= 1) s += __shfl_xor_sync(0xffffffffu, s, o);
    if (lane == 0) {
        float z = s + bfc[0];
        out[warp] = 1.0f / (1.0f + expf(-z));
    }
}

// ---------------------------------------------------------------------------
extern "C" void kernel_launch(void* const* d_in, const int* in_sizes, int n_in,
                              void* d_out, int out_size) {
    const int*   inputs = (const int*)  d_in[0];
    const float* emb    = (const float*)d_in[1];
    const float* Wx0    = (const float*)d_in[2];
    const float* Wh0    = (const float*)d_in[3];
    const float* b0     = (const float*)d_in[4];
    const float* Wx1    = (const float*)d_in[5];
    const float* Wh1    = (const float*)d_in[6];
    const float* b1     = (const float*)d_in[7];
    const float* Wfc    = (const float*)d_in[8];
    const float* bfc    = (const float*)d_in[9];
    float* out = (float*)d_out;

    cudaFuncSetAttribute(rnn_step_kernel,
                         cudaFuncAttributeMaxDynamicSharedMemorySize, SMEM_DYN);

    __half *wt, *h;
    float* xw0;
    cudaGetSymbolAddress((void**)&wt, g_wt);
    cudaGetSymbolAddress((void**)&xw0, g_xw0);
    cudaGetSymbolAddress((void**)&h, g_h);

    const size_t WS = (size_t)U_SZ * U_SZ;
    __half* Wh0q = wt + 0 * WS;
    __half* Wx1q = wt + 1 * WS;
    __half* Wh1q = wt + 2 * WS;

    const size_t HS = (size_t)B_SZ * U_SZ;
    __half* h0[2] = {h + 0 * HS, h + 1 * HS};
    __half* h1[2] = {h + 2 * HS, h + 3 * HS};

    transpose_split_kernel<<<dim3(32, 32, 3), 256>>>(Wh0, Wx1, Wh1);
    xw0_kernel<<<dim3(4, V_SZ / 16), 256>>>(emb, Wx0, b0, xw0);
    zero2_kernel<<<(unsigned)(HS / 8 / 256), 256>>>(h0[0], h1[0]);

    dim3 grid(U_SZ / BN, B_SZ / BM);   // (8, 32) = 256 CTAs

    int p0 = 0, p1 = 0;
    for (int t = 0; t < T_SZ; ++t) {
        rnn_step_kernel<<<grid, 128, SMEM_DYN>>>(
            h0[p0], Wh0q,
            nullptr, nullptr, 1,
            nullptr, xw0, inputs, t,
            h0[p0 ^ 1]);
        p0 ^= 1;
        rnn_step_kernel<<<grid, 128, SMEM_DYN>>>(
            h0[p0], Wx1q,
            h1[p1], Wh1q, 2,
            b1, nullptr, nullptr, 0,
            h1[p1 ^ 1]);
        p1 ^= 1;
    }

    final_kernel<<<B_SZ / 8, 256>>>(h1[p1], Wfc, bfc, out);
}